// round 2
// baseline (speedup 1.0000x reference)
#include <cuda_runtime.h>

#define BSZ 4
#define SEQ 256
#define DIM 128
#define HID 128
#define DFF 512
#define MROWS (BSZ*SEQ)   // 1024

// ---------------- scratch (device globals; no allocations) ----------------
__device__ float g_Wcat[DIM*2*HID];      // [128,256] = [W1q | W1k]
__device__ float g_bcat[2*HID];          // [b1 | 0]
__device__ float g_p1 [MROWS*DIM];
__device__ float g_pqk[2*MROWS*DIM];     // [pq ; pk]
__device__ float g_Tc [2*MROWS*2*HID];   // projected cat: rows x 256
__device__ float g_lgA[BSZ*SEQ*SEQ];     // sim partial, H-half 0
__device__ float g_lgB[BSZ*SEQ*SEQ];     // sim partial, H-half 1
__device__ float g_probs[BSZ*SEQ*SEQ];
__device__ float g_ctx[MROWS*DIM];
__device__ float g_out1[MROWS*DIM];
__device__ float g_out2[MROWS*DIM];
__device__ float g_fh [MROWS*DFF];

// ---------------- weight concat: Wcat = [W1q | W1k], bcat = [b1 | 0] -------
__global__ void build_cat_kernel(const float* __restrict__ W1q, const float* __restrict__ W1k,
                                 const float* __restrict__ b1,
                                 float* __restrict__ Wcat, float* __restrict__ bcat)
{
    int idx = blockIdx.x * 256 + threadIdx.x;   // 0..32767
    int k = idx >> 8, n = idx & 255;
    Wcat[idx] = (n < HID) ? W1q[k * HID + n] : W1k[k * HID + n - HID];
    if (idx < 2 * HID) bcat[idx] = (idx < HID) ? b1[idx] : 0.f;
}

// ---------------- SGEMM: 32x32 tile, 64 threads, 4x4 micro ----------------
// C = A[M,K] @ B[K,N] (+bias, relu). batched via z-strides; optional second
// A pointer A2 used when z==1 (for batching two independent GEMMs).
__global__ void sgemm_kernel(const float* __restrict__ A, const float* __restrict__ A2,
                             const float* __restrict__ B, const float* __restrict__ bias,
                             float* __restrict__ C,
                             int M, int N, int K, int relu,
                             long sA, long sB, long sC)
{
    __shared__ float As[32][36];   // [k][m], padded for float4 alignment
    __shared__ float Bs[32][36];   // [k][n]
    const float* Ab = (A2 && blockIdx.z) ? A2 : A + (long)blockIdx.z * sA;
    const float* Bb = B + (long)blockIdx.z * sB;
    float* Cb = C + (long)blockIdx.z * sC;
    int m0 = blockIdx.y * 32, n0 = blockIdx.x * 32;
    int tid = threadIdx.x;                 // 64 threads
    int tc = tid & 7, tr = tid >> 3;       // 8x8 thread grid, 4x4 micro
    float acc[4][4] = {};

    for (int k0 = 0; k0 < K; k0 += 32) {
        #pragma unroll
        for (int i = 0; i < 16; i++) {
            int idx = tid + i * 64;              // 0..1023
            int ka = idx & 31, ma = idx >> 5;    // A coalesced over k
            As[ka][ma] = Ab[(long)(m0 + ma) * K + k0 + ka];
            int nb = idx & 31, kb = idx >> 5;    // B coalesced over n
            Bs[kb][nb] = Bb[(long)(k0 + kb) * N + n0 + nb];
        }
        __syncthreads();
        #pragma unroll
        for (int kk = 0; kk < 32; kk++) {
            float4 a = *(const float4*)&As[kk][tr * 4];
            float4 b = *(const float4*)&Bs[kk][tc * 4];
            float av[4] = {a.x, a.y, a.z, a.w};
            float bv[4] = {b.x, b.y, b.z, b.w};
            #pragma unroll
            for (int i = 0; i < 4; i++)
                #pragma unroll
                for (int j = 0; j < 4; j++)
                    acc[i][j] += av[i] * bv[j];
        }
        __syncthreads();
    }
    int m = m0 + tr * 4, n = n0 + tc * 4;
    float bb[4] = {0.f, 0.f, 0.f, 0.f};
    if (bias) { float4 b4 = *(const float4*)&bias[n]; bb[0]=b4.x; bb[1]=b4.y; bb[2]=b4.z; bb[3]=b4.w; }
    #pragma unroll
    for (int i = 0; i < 4; i++) {
        float4 o4;
        float v0 = acc[i][0] + bb[0], v1 = acc[i][1] + bb[1];
        float v2 = acc[i][2] + bb[2], v3 = acc[i][3] + bb[3];
        if (relu) { v0=fmaxf(v0,0.f); v1=fmaxf(v1,0.f); v2=fmaxf(v2,0.f); v3=fmaxf(v3,0.f); }
        o4.x=v0; o4.y=v1; o4.z=v2; o4.w=v3;
        *(float4*)&Cb[(long)(m + i) * N + n] = o4;
    }
}

// ---------------- pairwise similarity ----------------
// Tq: q-side rows (stride 256): term1 array at col 0, term2 array at col 128.
// Tk: k-side rows (stride 256): term1 array at col 128, term2 array at col 0.
// z = b*2 + hh: hh selects H-half [hh*64, hh*64+64) -> partial into lgA/lgB.
// dual=0: term1 only (self-attn; symmetry handled in softmax).
__global__ void sim_kernel(const float* __restrict__ Tq, const float* __restrict__ Tk,
                           const float* __restrict__ W2,
                           float* __restrict__ lgA, float* __restrict__ lgB, int dual)
{
    __shared__ float sqa[32][34];  // term1 q-side [h][q]
    __shared__ float sqb[32][34];  // term2 q-side
    __shared__ float skb[32][68];  // term1 k-side [h][k]
    __shared__ float ska[32][68];  // term2 k-side
    __shared__ float sw[32];

    int z = blockIdx.z, b = z >> 1, hh = z & 1;
    int q0 = blockIdx.y * 32, k0 = blockIdx.x * 64;
    const float* pq = Tq + ((long)(b * SEQ + q0)) * 256;
    const float* pk = Tk + ((long)(b * SEQ + k0)) * 256;
    int tid = threadIdx.x;
    int tx = tid & 15, ty = tid >> 4;
    float acc[2][4] = {};

    #pragma unroll
    for (int hc = 0; hc < 2; hc++) {
        int h0 = hh * 64 + hc * 32;
        #pragma unroll
        for (int i = 0; i < 4; i++) {          // q-side: 32 rows x 32 h
            int idx = tid + i * 256;
            int r = idx >> 5, h = idx & 31;
            sqa[h][r] = pq[(long)r * 256 + h0 + h];
            if (dual) sqb[h][r] = pq[(long)r * 256 + 128 + h0 + h];
        }
        #pragma unroll
        for (int i = 0; i < 8; i++) {          // k-side: 64 rows x 32 h
            int idx = tid + i * 256;
            int r = idx >> 5, h = idx & 31;
            skb[h][r] = pk[(long)r * 256 + 128 + h0 + h];
            if (dual) ska[h][r] = pk[(long)r * 256 + h0 + h];
        }
        if (tid < 32) sw[tid] = W2[h0 + tid];
        __syncthreads();

        #pragma unroll 4
        for (int h = 0; h < 32; h++) {
            float w = sw[h];
            float2 a1r = *(const float2*)&sqa[h][ty * 2];
            float4 b1r = *(const float4*)&skb[h][tx * 4];
            float a1v[2] = {a1r.x, a1r.y};
            float b1v[4] = {b1r.x, b1r.y, b1r.z, b1r.w};
            #pragma unroll
            for (int i = 0; i < 2; i++)
                #pragma unroll
                for (int j = 0; j < 4; j++)
                    acc[i][j] += fmaxf(a1v[i] + b1v[j], 0.f) * w;
            if (dual) {
                float2 qb = *(const float2*)&sqb[h][ty * 2];
                float4 ka = *(const float4*)&ska[h][tx * 4];
                float qv[2] = {qb.x, qb.y};
                float kv[4] = {ka.x, ka.y, ka.z, ka.w};
                #pragma unroll
                for (int i = 0; i < 2; i++)
                    #pragma unroll
                    for (int j = 0; j < 4; j++)
                        acc[i][j] += fmaxf(kv[j] + qv[i], 0.f) * w;
            }
        }
        __syncthreads();
    }

    float* out = hh ? lgB : lgA;
    #pragma unroll
    for (int i = 0; i < 2; i++) {
        int q = q0 + ty * 2 + i;
        #pragma unroll
        for (int j = 0; j < 4; j++) {
            int k = k0 + tx * 4 + j;
            out[((long)b * SEQ + q) * SEQ + k] = acc[i][j];
        }
    }
}

// ---------------- masked softmax; sym adds transposed logits ---------------
__global__ void softmax_kernel(const float* __restrict__ lgA, const float* __restrict__ lgB,
                               const float* __restrict__ mask, const float* __restrict__ b2p,
                               float* __restrict__ probs, int sym)
{
    int q = blockIdx.x, b = blockIdx.y;
    long row = ((long)b * SEQ + q) * SEQ;
    int t = threadIdx.x;
    __shared__ float red[8];

    float x = lgA[row + t] + lgB[row + t];
    if (sym) {
        long col = ((long)b * SEQ + t) * SEQ + q;
        x += lgA[col] + lgB[col];
    }
    x += 2.f * b2p[0] + mask[row + t] * (-1e9f);

    float m = x;
    #pragma unroll
    for (int o = 16; o; o >>= 1) m = fmaxf(m, __shfl_xor_sync(0xffffffffu, m, o));
    if ((t & 31) == 0) red[t >> 5] = m;
    __syncthreads();
    m = red[0];
    #pragma unroll
    for (int i = 1; i < 8; i++) m = fmaxf(m, red[i]);

    float e = __expf(x - m);
    float s = e;
    #pragma unroll
    for (int o = 16; o; o >>= 1) s += __shfl_xor_sync(0xffffffffu, s, o);
    __syncthreads();
    if ((t & 31) == 0) red[t >> 5] = s;
    __syncthreads();
    s = red[0] + red[1] + red[2] + red[3] + red[4] + red[5] + red[6] + red[7];
    probs[row + t] = e / s;
}

// ---------------- fused GEMM + bias + residual + LayerNorm -----------------
// out[M,128] = LN( A[M,K]@B[K,128] + bias + res ). 8 rows/block, 64 threads.
__global__ void gemm_ln_kernel(const float* __restrict__ A, const float* __restrict__ B,
                               const float* __restrict__ bias, const float* __restrict__ res,
                               const float* __restrict__ g, const float* __restrict__ be,
                               float* __restrict__ out, int K)
{
    __shared__ float As[32][12];    // [k][m], 8 rows (pad 12: 8B align)
    __shared__ float Bs[32][132];   // [k][n]
    int m0 = blockIdx.x * 8;
    int tid = threadIdx.x;              // 64
    int tc = tid & 15, tr = tid >> 4;   // tc: 8 cols each; tr: 2 rows each
    float acc[2][8] = {};

    for (int k0 = 0; k0 < K; k0 += 32) {
        #pragma unroll
        for (int i = 0; i < 4; i++) {       // A: 8x32
            int idx = tid + i * 64;
            int k = idx & 31, mm = idx >> 5;
            As[k][mm] = A[(long)(m0 + mm) * K + k0 + k];
        }
        #pragma unroll
        for (int i = 0; i < 16; i++) {      // B: 32x128 as float4
            int idx = tid + i * 64;         // 0..1023
            int n4 = idx & 31, kb = idx >> 5;
            float4 v = *(const float4*)&B[(long)(k0 + kb) * 128 + n4 * 4];
            *(float4*)&Bs[kb][n4 * 4] = v;
        }
        __syncthreads();
        #pragma unroll
        for (int kk = 0; kk < 32; kk++) {
            float2 a = *(const float2*)&As[kk][tr * 2];
            float4 b0 = *(const float4*)&Bs[kk][tc * 8];
            float4 b1 = *(const float4*)&Bs[kk][tc * 8 + 4];
            float bv[8] = {b0.x, b0.y, b0.z, b0.w, b1.x, b1.y, b1.z, b1.w};
            #pragma unroll
            for (int j = 0; j < 8; j++) {
                acc[0][j] += a.x * bv[j];
                acc[1][j] += a.y * bv[j];
            }
        }
        __syncthreads();
    }

    // epilogue: two rows per thread, each row owned by 16 lanes (same tr)
    #pragma unroll
    for (int i = 0; i < 2; i++) {
        int r = m0 + tr * 2 + i;
        float v[8];
        #pragma unroll
        for (int j = 0; j < 8; j++)
            v[j] = acc[i][j] + bias[tc * 8 + j] + res[(long)r * 128 + tc * 8 + j];
        float s = 0.f;
        #pragma unroll
        for (int j = 0; j < 8; j++) s += v[j];
        #pragma unroll
        for (int o = 8; o; o >>= 1) s += __shfl_xor_sync(0xffffffffu, s, o, 16);
        float mean = s * (1.f / 128.f);
        float vs = 0.f;
        #pragma unroll
        for (int j = 0; j < 8; j++) { float d = v[j] - mean; vs += d * d; }
        #pragma unroll
        for (int o = 8; o; o >>= 1) vs += __shfl_xor_sync(0xffffffffu, vs, o, 16);
        float inv = rsqrtf(vs * (1.f / 128.f) + 1e-6f);
        #pragma unroll
        for (int j = 0; j < 8; j++) {
            int n = tc * 8 + j;
            out[(long)r * 128 + n] = (v[j] - mean) * inv * g[n] + be[n];
        }
    }
}

// ---------------- host orchestration ----------------
static inline void G(const float* A, const float* A2, const float* B, const float* bias,
                     float* C, int M, int N, int K, int relu, int batch,
                     long sA, long sB, long sC)
{
    dim3 grid(N / 32, M / 32, batch);
    sgemm_kernel<<<grid, 64>>>(A, A2, B, bias, C, M, N, K, relu, sA, sB, sC);
}

extern "C" void kernel_launch(void* const* d_in, const int* in_sizes, int n_in,
                              void* d_out, int out_size)
{
    (void)in_sizes; (void)n_in; (void)out_size;
    const float* x    = (const float*)d_in[0];
    const float* enc  = (const float*)d_in[1];
    const float* cmsk = (const float*)d_in[2];
    const float* dmsk = (const float*)d_in[3];
    const float* W1q  = (const float*)d_in[4];
    const float* W1k  = (const float*)d_in[5];
    const float* b1   = (const float*)d_in[6];
    const float* W2   = (const float*)d_in[7];
    const float* b2   = (const float*)d_in[8];
    const float* Ww1  = (const float*)d_in[9];
    const float* bw1  = (const float*)d_in[10];
    const float* Wd1  = (const float*)d_in[11];
    const float* bd1  = (const float*)d_in[12];
    const float* Ww2  = (const float*)d_in[13];
    const float* bw2  = (const float*)d_in[14];
    const float* Wd2  = (const float*)d_in[15];
    const float* bd2  = (const float*)d_in[16];
    const float* Wf1  = (const float*)d_in[17];
    const float* bf1  = (const float*)d_in[18];
    const float* Wf2  = (const float*)d_in[19];
    const float* bf2  = (const float*)d_in[20];
    const float* ln1g = (const float*)d_in[21];
    const float* ln1b = (const float*)d_in[22];
    const float* ln2g = (const float*)d_in[23];
    const float* ln2b = (const float*)d_in[24];
    const float* ln3g = (const float*)d_in[25];
    const float* ln3b = (const float*)d_in[26];
    float* out = (float*)d_out;

    float *Wcat, *bcat, *p1, *pqk, *Tc, *lgA, *lgB, *probs, *ctx, *o1, *o2, *fh;
    cudaGetSymbolAddress((void**)&Wcat,  g_Wcat);
    cudaGetSymbolAddress((void**)&bcat,  g_bcat);
    cudaGetSymbolAddress((void**)&p1,    g_p1);
    cudaGetSymbolAddress((void**)&pqk,   g_pqk);
    cudaGetSymbolAddress((void**)&Tc,    g_Tc);
    cudaGetSymbolAddress((void**)&lgA,   g_lgA);
    cudaGetSymbolAddress((void**)&lgB,   g_lgB);
    cudaGetSymbolAddress((void**)&probs, g_probs);
    cudaGetSymbolAddress((void**)&ctx,   g_ctx);
    cudaGetSymbolAddress((void**)&o1,    g_out1);
    cudaGetSymbolAddress((void**)&o2,    g_out2);
    cudaGetSymbolAddress((void**)&fh,    g_fh);

    dim3 simGrid(SEQ / 64, SEQ / 32, BSZ * 2);
    dim3 smGrid(SEQ, BSZ);

    build_cat_kernel<<<DIM * 2 * HID / 256, 256>>>(W1q, W1k, b1, Wcat, bcat);

    // ---- self-attention: q=k=v = x@Ww1+bw1; logits = S + S^T (symmetry) ----
    G(x,  0, Ww1, bw1, p1, MROWS, DIM, DIM, 0, 1, 0, 0, 0);
    G(p1, 0, Wcat, bcat, Tc, MROWS, 2 * HID, DIM, 0, 1, 0, 0, 0);
    sim_kernel<<<simGrid, 256>>>(Tc, Tc, W2, lgA, lgB, 0);
    softmax_kernel<<<smGrid, 256>>>(lgA, lgB, cmsk, b2, probs, 1);
    G(probs, 0, p1, 0, ctx, SEQ, DIM, SEQ, 0, BSZ,
      (long)SEQ * SEQ, (long)SEQ * DIM, (long)SEQ * DIM);
    gemm_ln_kernel<<<MROWS / 8, 64>>>(ctx, Wd1, bd1, x, ln1g, ln1b, o1, DIM);

    // ---- cross-attention: q = o1 proj, k=v = enc proj ----
    G(o1, enc, Ww2, bw2, pqk, MROWS, DIM, DIM, 0, 2, 0, 0, (long)MROWS * DIM);
    G(pqk, 0, Wcat, bcat, Tc, 2 * MROWS, 2 * HID, DIM, 0, 1, 0, 0, 0);
    sim_kernel<<<simGrid, 256>>>(Tc, Tc + (long)MROWS * 2 * HID, W2, lgA, lgB, 1);
    softmax_kernel<<<smGrid, 256>>>(lgA, lgB, dmsk, b2, probs, 0);
    G(probs, 0, pqk + (long)MROWS * DIM, 0, ctx, SEQ, DIM, SEQ, 0, BSZ,
      (long)SEQ * SEQ, (long)SEQ * DIM, (long)SEQ * DIM);
    gemm_ln_kernel<<<MROWS / 8, 64>>>(ctx, Wd2, bd2, o1, ln2g, ln2b, o2, DIM);

    // ---- FFN ----
    G(o2, 0, Wf1, bf1, fh, MROWS, DFF, DIM, 1, 1, 0, 0, 0);
    gemm_ln_kernel<<<MROWS / 8, 64>>>(fh, Wf2, bf2, o2, ln3g, ln3b, out, DFF);
}

// round 3
// speedup vs baseline: 1.2581x; 1.2581x over previous
#include <cuda_runtime.h>

#define BSZ 4
#define SEQ 256
#define DIM 128
#define HID 128
#define DFF 512
#define MROWS (BSZ*SEQ)   // 1024
#define LGSZ (BSZ*SEQ*SEQ)

// ---------------- scratch (device globals; no allocations) ----------------
__device__ float g_Wcat[DIM*2*HID];      // [128,256] = [W1q | W1k]
__device__ float g_bcat[2*HID];          // [b1 | 0]
__device__ float g_p1 [MROWS*DIM];
__device__ float g_pqk[2*MROWS*DIM];     // [pq ; pk]
__device__ float g_Tc [2*MROWS*2*HID];   // projected cat: rows x 256
__device__ float g_lg [4*LGSZ];          // sim partials, 4 H-quarters
__device__ float g_probs[LGSZ];
__device__ float g_ctx[MROWS*DIM];
__device__ float g_tmp[MROWS*DIM];
__device__ float g_out1[MROWS*DIM];
__device__ float g_out2[MROWS*DIM];
__device__ float g_fh [MROWS*DFF];

// ---------------- weight concat: Wcat = [W1q | W1k], bcat = [b1 | 0] -------
__global__ void build_cat_kernel(const float* __restrict__ W1q, const float* __restrict__ W1k,
                                 const float* __restrict__ b1,
                                 float* __restrict__ Wcat, float* __restrict__ bcat)
{
    int idx = blockIdx.x * 256 + threadIdx.x;   // 0..32767
    int k = idx >> 8, n = idx & 255;
    Wcat[idx] = (n < HID) ? W1q[k * HID + n] : W1k[k * HID + n - HID];
    if (idx < 2 * HID) bcat[idx] = (idx < HID) ? b1[idx] : 0.f;
}

// ---------------- SGEMM: 32x32 tile, 256 threads, 2x2 micro (R1-proven) ----
// C = A[M,K] @ B[K,N] (+bias, relu), batched strides; A2 used when z==1.
__global__ void sgemm_kernel(const float* __restrict__ A, const float* __restrict__ A2,
                             const float* __restrict__ B, const float* __restrict__ bias,
                             float* __restrict__ C,
                             int M, int N, int K, int relu,
                             long sA, long sB, long sC)
{
    __shared__ float As[32][34];   // [k][m]
    __shared__ float Bs[32][34];   // [k][n]
    const float* Ab = (A2 && blockIdx.z) ? A2 : A + (long)blockIdx.z * sA;
    const float* Bb = B + (long)blockIdx.z * sB;
    float* Cb = C + (long)blockIdx.z * sC;
    int m0 = blockIdx.y * 32, n0 = blockIdx.x * 32;
    int tid = threadIdx.x;
    int tx = tid & 15, ty = tid >> 4;
    float acc00 = 0.f, acc01 = 0.f, acc10 = 0.f, acc11 = 0.f;

    for (int k0 = 0; k0 < K; k0 += 32) {
        #pragma unroll
        for (int i = 0; i < 4; i++) {
            int idx = tid + i * 256;           // 0..1023
            int ka = idx & 31, ma = idx >> 5;  // A: coalesced over k
            As[ka][ma] = Ab[(long)(m0 + ma) * K + k0 + ka];
            int nb = idx & 31, kb = idx >> 5;  // B: coalesced over n
            Bs[kb][nb] = Bb[(long)(k0 + kb) * N + n0 + nb];
        }
        __syncthreads();
        #pragma unroll
        for (int kk = 0; kk < 32; kk++) {
            float2 a = *(const float2*)&As[kk][ty * 2];
            float2 b = *(const float2*)&Bs[kk][tx * 2];
            acc00 += a.x * b.x; acc01 += a.x * b.y;
            acc10 += a.y * b.x; acc11 += a.y * b.y;
        }
        __syncthreads();
    }
    int m = m0 + ty * 2, n = n0 + tx * 2;
    float bb0 = bias ? bias[n]     : 0.f;
    float bb1 = bias ? bias[n + 1] : 0.f;
    float v00 = acc00 + bb0, v01 = acc01 + bb1;
    float v10 = acc10 + bb0, v11 = acc11 + bb1;
    if (relu) {
        v00 = fmaxf(v00, 0.f); v01 = fmaxf(v01, 0.f);
        v10 = fmaxf(v10, 0.f); v11 = fmaxf(v11, 0.f);
    }
    Cb[(long)m * N + n]           = v00;
    Cb[(long)m * N + n + 1]       = v01;
    Cb[(long)(m + 1) * N + n]     = v10;
    Cb[(long)(m + 1) * N + n + 1] = v11;
}

// ---------------- pairwise similarity ----------------
// Tq/Tk rows have stride 256: [q@W1q + b1 | q@W1k].
// term1[q,k] = relu(Tq[q,0:128] + Tk[k,128:256]) . W2
// term2[q,k] = relu(Tk[k,0:128] + Tq[q,128:256]) . W2   (dual=1 only)
// z = b*4 + hq: H-quarter [hq*32, hq*32+32) -> partial into lg + hq*LGSZ.
__global__ void sim_kernel(const float* __restrict__ Tq, const float* __restrict__ Tk,
                           const float* __restrict__ W2,
                           float* __restrict__ lg, int dual)
{
    __shared__ float sqa[32][34];  // term1 q-side [h][q]
    __shared__ float sqb[32][34];  // term2 q-side
    __shared__ float skb[32][68];  // term1 k-side [h][k]
    __shared__ float ska[32][68];  // term2 k-side
    __shared__ float sw[32];

    int z = blockIdx.z, b = z >> 2, hq = z & 3;
    int h0 = hq * 32;
    int q0 = blockIdx.y * 32, k0 = blockIdx.x * 64;
    const float* pq = Tq + ((long)(b * SEQ + q0)) * 256;
    const float* pk = Tk + ((long)(b * SEQ + k0)) * 256;
    int tid = threadIdx.x;
    int tx = tid & 15, ty = tid >> 4;
    float acc[2][4] = {};

    #pragma unroll
    for (int i = 0; i < 4; i++) {          // q-side: 32 rows x 32 h
        int idx = tid + i * 256;
        int r = idx >> 5, h = idx & 31;
        sqa[h][r] = pq[(long)r * 256 + h0 + h];
        if (dual) sqb[h][r] = pq[(long)r * 256 + 128 + h0 + h];
    }
    #pragma unroll
    for (int i = 0; i < 8; i++) {          // k-side: 64 rows x 32 h
        int idx = tid + i * 256;
        int r = idx >> 5, h = idx & 31;
        skb[h][r] = pk[(long)r * 256 + 128 + h0 + h];
        if (dual) ska[h][r] = pk[(long)r * 256 + h0 + h];
    }
    if (tid < 32) sw[tid] = W2[h0 + tid];
    __syncthreads();

    #pragma unroll 4
    for (int h = 0; h < 32; h++) {
        float w = sw[h];
        float2 a1r = *(const float2*)&sqa[h][ty * 2];
        float4 b1r = *(const float4*)&skb[h][tx * 4];
        float a1v[2] = {a1r.x, a1r.y};
        float b1v[4] = {b1r.x, b1r.y, b1r.z, b1r.w};
        #pragma unroll
        for (int i = 0; i < 2; i++)
            #pragma unroll
            for (int j = 0; j < 4; j++)
                acc[i][j] += fmaxf(a1v[i] + b1v[j], 0.f) * w;
        if (dual) {
            float2 qb = *(const float2*)&sqb[h][ty * 2];
            float4 ka = *(const float4*)&ska[h][tx * 4];
            float qv[2] = {qb.x, qb.y};
            float kv[4] = {ka.x, ka.y, ka.z, ka.w};
            #pragma unroll
            for (int i = 0; i < 2; i++)
                #pragma unroll
                for (int j = 0; j < 4; j++)
                    acc[i][j] += fmaxf(kv[j] + qv[i], 0.f) * w;
        }
    }

    float* out = lg + (long)hq * LGSZ;
    #pragma unroll
    for (int i = 0; i < 2; i++) {
        int q = q0 + ty * 2 + i;
        #pragma unroll
        for (int j = 0; j < 4; j++) {
            int k = k0 + tx * 4 + j;
            out[((long)b * SEQ + q) * SEQ + k] = acc[i][j];
        }
    }
}

// ---------------- masked softmax; sums 4 H-partials; sym adds transpose ----
__global__ void softmax_kernel(const float* __restrict__ lg,
                               const float* __restrict__ mask, const float* __restrict__ b2p,
                               float* __restrict__ probs, int sym)
{
    int q = blockIdx.x, b = blockIdx.y;
    long row = ((long)b * SEQ + q) * SEQ;
    int t = threadIdx.x;
    __shared__ float red[8];

    float x = 0.f;
    #pragma unroll
    for (int p = 0; p < 4; p++) x += lg[(long)p * LGSZ + row + t];
    if (sym) {
        long col = ((long)b * SEQ + t) * SEQ + q;
        #pragma unroll
        for (int p = 0; p < 4; p++) x += lg[(long)p * LGSZ + col];
    }
    x += 2.f * b2p[0] + mask[row + t] * (-1e9f);

    float m = x;
    #pragma unroll
    for (int o = 16; o; o >>= 1) m = fmaxf(m, __shfl_xor_sync(0xffffffffu, m, o));
    if ((t & 31) == 0) red[t >> 5] = m;
    __syncthreads();
    m = red[0];
    #pragma unroll
    for (int i = 1; i < 8; i++) m = fmaxf(m, red[i]);

    float e = __expf(x - m);
    float s = e;
    #pragma unroll
    for (int o = 16; o; o >>= 1) s += __shfl_xor_sync(0xffffffffu, s, o);
    __syncthreads();
    if ((t & 31) == 0) red[t >> 5] = s;
    __syncthreads();
    s = red[0] + red[1] + red[2] + red[3] + red[4] + red[5] + red[6] + red[7];
    probs[row + t] = e / s;
}

// ---------------- fused residual add + LayerNorm (warp per 128-row) --------
__global__ void add_ln_kernel(const float* __restrict__ a, const float* __restrict__ r,
                              const float* __restrict__ g, const float* __restrict__ be,
                              float* __restrict__ out)
{
    int row  = blockIdx.x * 8 + (threadIdx.x >> 5);
    int lane = threadIdx.x & 31;
    long base = (long)row * DIM + lane * 4;
    float4 av = *(const float4*)(a + base);
    float4 rv = *(const float4*)(r + base);
    float v[4] = {av.x + rv.x, av.y + rv.y, av.z + rv.z, av.w + rv.w};
    float s = v[0] + v[1] + v[2] + v[3];
    #pragma unroll
    for (int o = 16; o; o >>= 1) s += __shfl_xor_sync(0xffffffffu, s, o);
    float mean = s * (1.f / DIM);
    float vs = 0.f;
    #pragma unroll
    for (int j = 0; j < 4; j++) { float d = v[j] - mean; vs += d * d; }
    #pragma unroll
    for (int o = 16; o; o >>= 1) vs += __shfl_xor_sync(0xffffffffu, vs, o);
    float inv = rsqrtf(vs * (1.f / DIM) + 1e-6f);
    float4 gv = *(const float4*)(g + lane * 4);
    float4 bv = *(const float4*)(be + lane * 4);
    float4 o4;
    o4.x = (v[0] - mean) * inv * gv.x + bv.x;
    o4.y = (v[1] - mean) * inv * gv.y + bv.y;
    o4.z = (v[2] - mean) * inv * gv.z + bv.z;
    o4.w = (v[3] - mean) * inv * gv.w + bv.w;
    *(float4*)(out + base) = o4;
}

// ---------------- host orchestration ----------------
static inline void G(const float* A, const float* A2, const float* B, const float* bias,
                     float* C, int M, int N, int K, int relu, int batch,
                     long sA, long sB, long sC)
{
    dim3 grid(N / 32, M / 32, batch);
    sgemm_kernel<<<grid, 256>>>(A, A2, B, bias, C, M, N, K, relu, sA, sB, sC);
}

extern "C" void kernel_launch(void* const* d_in, const int* in_sizes, int n_in,
                              void* d_out, int out_size)
{
    (void)in_sizes; (void)n_in; (void)out_size;
    const float* x    = (const float*)d_in[0];
    const float* enc  = (const float*)d_in[1];
    const float* cmsk = (const float*)d_in[2];
    const float* dmsk = (const float*)d_in[3];
    const float* W1q  = (const float*)d_in[4];
    const float* W1k  = (const float*)d_in[5];
    const float* b1   = (const float*)d_in[6];
    const float* W2   = (const float*)d_in[7];
    const float* b2   = (const float*)d_in[8];
    const float* Ww1  = (const float*)d_in[9];
    const float* bw1  = (const float*)d_in[10];
    const float* Wd1  = (const float*)d_in[11];
    const float* bd1  = (const float*)d_in[12];
    const float* Ww2  = (const float*)d_in[13];
    const float* bw2  = (const float*)d_in[14];
    const float* Wd2  = (const float*)d_in[15];
    const float* bd2  = (const float*)d_in[16];
    const float* Wf1  = (const float*)d_in[17];
    const float* bf1  = (const float*)d_in[18];
    const float* Wf2  = (const float*)d_in[19];
    const float* bf2  = (const float*)d_in[20];
    const float* ln1g = (const float*)d_in[21];
    const float* ln1b = (const float*)d_in[22];
    const float* ln2g = (const float*)d_in[23];
    const float* ln2b = (const float*)d_in[24];
    const float* ln3g = (const float*)d_in[25];
    const float* ln3b = (const float*)d_in[26];
    float* out = (float*)d_out;

    float *Wcat, *bcat, *p1, *pqk, *Tc, *lg, *probs, *ctx, *tmp, *o1, *o2, *fh;
    cudaGetSymbolAddress((void**)&Wcat,  g_Wcat);
    cudaGetSymbolAddress((void**)&bcat,  g_bcat);
    cudaGetSymbolAddress((void**)&p1,    g_p1);
    cudaGetSymbolAddress((void**)&pqk,   g_pqk);
    cudaGetSymbolAddress((void**)&Tc,    g_Tc);
    cudaGetSymbolAddress((void**)&lg,    g_lg);
    cudaGetSymbolAddress((void**)&probs, g_probs);
    cudaGetSymbolAddress((void**)&ctx,   g_ctx);
    cudaGetSymbolAddress((void**)&tmp,   g_tmp);
    cudaGetSymbolAddress((void**)&o1,    g_out1);
    cudaGetSymbolAddress((void**)&o2,    g_out2);
    cudaGetSymbolAddress((void**)&fh,    g_fh);

    dim3 simGrid(SEQ / 64, SEQ / 32, BSZ * 4);
    dim3 smGrid(SEQ, BSZ);

    build_cat_kernel<<<DIM * 2 * HID / 256, 256>>>(W1q, W1k, b1, Wcat, bcat);

    // ---- self-attention: q=k=v = x@Ww1+bw1; logits = S + S^T (symmetry) ----
    G(x,  0, Ww1, bw1, p1, MROWS, DIM, DIM, 0, 1, 0, 0, 0);
    G(p1, 0, Wcat, bcat, Tc, MROWS, 2 * HID, DIM, 0, 1, 0, 0, 0);
    sim_kernel<<<simGrid, 256>>>(Tc, Tc, W2, lg, 0);
    softmax_kernel<<<smGrid, 256>>>(lg, cmsk, b2, probs, 1);
    G(probs, 0, p1, 0, ctx, SEQ, DIM, SEQ, 0, BSZ,
      (long)SEQ * SEQ, (long)SEQ * DIM, (long)SEQ * DIM);
    G(ctx, 0, Wd1, bd1, tmp, MROWS, DIM, DIM, 0, 1, 0, 0, 0);
    add_ln_kernel<<<MROWS / 8, 256>>>(tmp, x, ln1g, ln1b, o1);

    // ---- cross-attention: q = o1 proj, k=v = enc proj ----
    G(o1, enc, Ww2, bw2, pqk, MROWS, DIM, DIM, 0, 2, 0, 0, (long)MROWS * DIM);
    G(pqk, 0, Wcat, bcat, Tc, 2 * MROWS, 2 * HID, DIM, 0, 1, 0, 0, 0);
    sim_kernel<<<simGrid, 256>>>(Tc, Tc + (long)MROWS * 2 * HID, W2, lg, 1);
    softmax_kernel<<<smGrid, 256>>>(lg, dmsk, b2, probs, 0);
    G(probs, 0, pqk + (long)MROWS * DIM, 0, ctx, SEQ, DIM, SEQ, 0, BSZ,
      (long)SEQ * SEQ, (long)SEQ * DIM, (long)SEQ * DIM);
    G(ctx, 0, Wd2, bd2, tmp, MROWS, DIM, DIM, 0, 1, 0, 0, 0);
    add_ln_kernel<<<MROWS / 8, 256>>>(tmp, o1, ln2g, ln2b, o2);

    // ---- FFN ----
    G(o2, 0, Wf1, bf1, fh, MROWS, DFF, DIM, 1, 1, 0, 0, 0);
    G(fh, 0, Wf2, bf2, tmp, MROWS, DIM, DFF, 0, 1, 0, 0, 0);
    add_ln_kernel<<<MROWS / 8, 256>>>(tmp, o2, ln3g, ln3b, out);
}